// round 11
// baseline (speedup 1.0000x reference)
#include <cuda_runtime.h>

#define TOL_F 1e-6f
#define LOSS_EPS_F 1e-6f
#define MAX_BLOCKS 8192

__device__ float g_partial[MAX_BLOCKS];
__device__ unsigned g_arrived = 0;

__global__ __launch_bounds__(256)
void diou3d_loss_kernel(const float* __restrict__ pred,
                        const float* __restrict__ tgt,
                        float* __restrict__ out, int n)
{
    int i = blockIdx.x * blockDim.x + threadIdx.x;
    float loss = 0.0f;
    if (i < n) {
        float p[7], t[7];
#pragma unroll
        for (int k = 0; k < 7; k++) { p[k] = pred[i * 7 + k]; t[k] = tgt[i * 7 + k]; }

        float cp, sp, ct, st;
        __sincosf(p[6], &sp, &cp);
        __sincosf(t[6], &st, &ct);

        // ---- box2's axis-aligned frame ----
        float W = 0.5f * t[3], H = 0.5f * t[4];
        float w1h = 0.5f * p[3], h1h = 0.5f * p[4];
        float cd = cp * ct + sp * st;                     // cos(a1-a2)
        float sd = sp * ct - cp * st;                     // sin(a1-a2)
        float dx0 = p[0] - t[0], dy0 = p[1] - t[1];
        float qx =  ct * dx0 + st * dy0;
        float qy = -st * dx0 + ct * dy0;

        // box1 corners in frame2 (reference order: (+,+)(-,+)(-,-)(+,-))
        float c1x[4], c1y[4];
        {
            const float sx[4] = {1.0f, -1.0f, -1.0f, 1.0f};
            const float sy[4] = {1.0f, 1.0f, -1.0f, -1.0f};
#pragma unroll
            for (int k = 0; k < 4; k++) {
                float ox = sx[k] * w1h, oy = sy[k] * h1h;
                c1x[k] = qx + ox * cd - oy * sd;
                c1y[k] = qy + ox * sd + oy * cd;
            }
        }

        float2 vv[24];
        int cnt = 0;
        float sumx = 0.0f, sumy = 0.0f;

        // corners of box1 inside box2
        {
            float bx = fmaf(TOL_F, t[3], W);
            float by = fmaf(TOL_F, t[4], H);
#pragma unroll
            for (int k = 0; k < 4; k++) {
                if (fabsf(c1x[k]) < bx && fabsf(c1y[k]) < by) {
                    vv[cnt] = make_float2(c1x[k], c1y[k]);
                    sumx += c1x[k]; sumy += c1y[k]; cnt++;
                }
            }
        }
        // corners of box2 inside box1
        {
            float bx = fmaf(TOL_F, p[3], w1h);
            float by = fmaf(TOL_F, p[4], h1h);
            const float kxs[4] = {1.0f, -1.0f, -1.0f, 1.0f};
            const float kys[4] = {1.0f, 1.0f, -1.0f, -1.0f};
#pragma unroll
            for (int k = 0; k < 4; k++) {
                float kx = kxs[k] * W, ky = kys[k] * H;
                float rx = kx - qx, ry = ky - qy;
                float mx = cd * rx + sd * ry;
                float my = -sd * rx + cd * ry;
                if (fabsf(mx) < bx && fabsf(my) < by) {
                    vv[cnt] = make_float2(kx, ky);
                    sumx += kx; sumy += ky; cnt++;
                }
            }
        }

        // box1 edges vs box2 edge lines with the reference's sign-flipped u:
        // accept iff t in (0,1) and u_ref = -u_true in (0,1)  (phantom windows):
        //   x=+W : yv in (-3H,-H)   x=-W : yv in (H,3H)
        //   y=+H : xv in (W,3W)     y=-H : xv in (-3W,-W)
        float W3 = 3.0f * W, H3 = 3.0f * H;
#pragma unroll
        for (int a = 0; a < 4; a++) {
            float x1 = c1x[a], y1 = c1y[a];
            float dxe = c1x[(a + 1) & 3] - x1, dye = c1y[(a + 1) & 3] - y1;
            float rdx = __fdividef(1.0f, dxe);   // 0 -> inf -> tests fail (num==0)
            float rdy = __fdividef(1.0f, dye);

            float tt = (W - x1) * rdx;
            if (tt > 0.0f && tt < 1.0f) {
                float yv = fmaf(tt, dye, y1);
                if (yv > -H3 && yv < -H) {
                    vv[cnt] = make_float2(W, yv);
                    sumx += W; sumy += yv; cnt++;
                }
            }
            tt = (-W - x1) * rdx;
            if (tt > 0.0f && tt < 1.0f) {
                float yv = fmaf(tt, dye, y1);
                if (yv > H && yv < H3) {
                    vv[cnt] = make_float2(-W, yv);
                    sumx += -W; sumy += yv; cnt++;
                }
            }
            tt = (H - y1) * rdy;
            if (tt > 0.0f && tt < 1.0f) {
                float xv = fmaf(tt, dxe, x1);
                if (xv > W && xv < W3) {
                    vv[cnt] = make_float2(xv, H);
                    sumx += xv; sumy += H; cnt++;
                }
            }
            tt = (-H - y1) * rdy;
            if (tt > 0.0f && tt < 1.0f) {
                float xv = fmaf(tt, dxe, x1);
                if (xv > -W3 && xv < -W) {
                    vv[cnt] = make_float2(xv, -H);
                    sumx += xv; sumy += -H; cnt++;
                }
            }
        }

        // ---- area via angular-successor permutation (no sort) ----
        // area = 0.5 * | sum_k cross(v_k - m, v_succ(k) - m) |, succ = cyclically
        // next pseudo-angle key. All-pairs argmin: independent ops, no serial chain.
        float area = 0.0f;
        if (cnt > 0) {
            unsigned key[24];
            float inv = __fdividef(1.0f, (float)cnt);
            float mx = sumx * inv, my = sumy * inv;
            for (int k = 0; k < cnt; k++) {
                float x = vv[k].x - mx, y = vv[k].y - my;
                // pseudo-angle in [0,4): same cyclic order as atan2
                float tt = __fdividef(x, fabsf(x) + fabsf(y) + 1e-30f);
                float a = (y >= 0.0f) ? (1.0f - tt) : (3.0f + tt);
                key[k] = (__float_as_uint(a) & 0xFFFFFFE0u) | (unsigned)k;  // unique
            }
            float s = 0.0f;
            for (int k = 0; k < cnt; k++) {
                unsigned kk = key[k];
                unsigned best = 0xFFFFFFFFu;
                int bj = k;
                for (int j = 0; j < cnt; j++) {
                    unsigned d = key[j] - kk - 1u;   // j==k -> 0xFFFFFFFF (excluded)
                    if (d < best) { best = d; bj = j; }
                }
                float ax = vv[k].x - mx,  ay = vv[k].y - my;
                float bx2 = vv[bj].x - mx, by2 = vv[bj].y - my;
                s += ax * by2 - ay * bx2;
            }
            area = 0.5f * fabsf(s);
        }

        // ---- 3D IoU ----
        float zov = fmaxf(fminf(p[2] + 0.5f * p[5], t[2] + 0.5f * t[5]) -
                          fmaxf(p[2] - 0.5f * p[5], t[2] - 0.5f * t[5]), 0.0f);
        float inter3 = area * zov;
        float vol1 = p[3] * p[4] * p[5];
        float vol2 = t[3] * t[4] * t[5];
        float iou = inter3 / (vol1 + vol2 - inter3);
        if (isnan(iou)) iou = 0.0f;

        float ctd = dx0 * dx0 + dy0 * dy0 + (p[2] - t[2]) * (p[2] - t[2]);

        // closed-form corner distance (verified R5)
        float alpha = p[3] * cp - t[3] * ct;
        float gamma = p[3] * sp - t[3] * st;
        float beta  = p[5] * sp - t[5] * st;
        float delta = p[5] * cp - t[5] * ct;
        float epsi  = p[4] - t[4];
        float cnd = ctd + 0.25f * (alpha * alpha + beta * beta + gamma * gamma +
                                   delta * delta + epsi * epsi);

        float did = t[3] * t[3] + t[4] * t[4] + t[5] * t[5];
        float sreg = ctd + cnd;
        float reg = __fdividef(sreg, sreg + did + LOSS_EPS_F);
        loss = 1.0f - iou + reg;
    }

    // ---- block reduction ----
#pragma unroll
    for (int off = 16; off; off >>= 1)
        loss += __shfl_down_sync(0xffffffff, loss, off);

    __shared__ float warpsum[8];
    int lane = threadIdx.x & 31, wid = threadIdx.x >> 5;
    if (lane == 0) warpsum[wid] = loss;
    __syncthreads();

    __shared__ bool amLast;
    if (wid == 0) {
        float s = (lane < 8) ? warpsum[lane] : 0.0f;
#pragma unroll
        for (int off = 4; off; off >>= 1)
            s += __shfl_down_sync(0xffffffff, s, off);
        if (lane == 0) {
            g_partial[blockIdx.x] = s;
            __threadfence();
            unsigned prev = atomicAdd(&g_arrived, 1u);
            amLast = (prev == gridDim.x - 1);
        }
    }
    __syncthreads();

    // last block: reduce all partials, write result, reset counter
    if (amLast) {
        int nb = gridDim.x;
        float s = 0.0f;
        for (int k = threadIdx.x; k < nb; k += 256) s += g_partial[k];
#pragma unroll
        for (int off = 16; off; off >>= 1)
            s += __shfl_down_sync(0xffffffff, s, off);
        if (lane == 0) warpsum[wid] = s;
        __syncthreads();
        if (wid == 0) {
            float s2 = (lane < 8) ? warpsum[lane] : 0.0f;
#pragma unroll
            for (int off = 4; off; off >>= 1)
                s2 += __shfl_down_sync(0xffffffff, s2, off);
            if (lane == 0) {
                out[0] = s2 * (1.0f / (float)n);
                g_arrived = 0;   // reset for next graph replay
            }
        }
    }
}

extern "C" void kernel_launch(void* const* d_in, const int* in_sizes, int n_in,
                              void* d_out, int out_size)
{
    const float* pred = (const float*)d_in[0];
    const float* tgt  = (const float*)d_in[1];
    float* out = (float*)d_out;
    int n = in_sizes[0] / 7;
    int blocks = (n + 255) / 256;
    if (blocks > MAX_BLOCKS) blocks = MAX_BLOCKS;  // n fixed at 262144 -> 1024

    diou3d_loss_kernel<<<blocks, 256>>>(pred, tgt, out, n);
}

// round 12
// speedup vs baseline: 1.1083x; 1.1083x over previous
#include <cuda_runtime.h>

#define TOL_F 1e-6f
#define LOSS_EPS_F 1e-6f
#define MAX_BLOCKS 8192

__device__ float g_partial[MAX_BLOCKS];
__device__ unsigned g_arrived = 0;

__constant__ float c_inv[32] = {
    1.0f, 1.0f, 0.5f, 1.0f/3, 0.25f, 0.2f, 1.0f/6, 1.0f/7,
    0.125f, 1.0f/9, 0.1f, 1.0f/11, 1.0f/12, 1.0f/13, 1.0f/14, 1.0f/15,
    0.0625f, 1.0f/17, 1.0f/18, 1.0f/19, 0.05f, 1.0f/21, 1.0f/22, 1.0f/23,
    1.0f/24, 1.0f/25, 1.0f/26, 1.0f/27, 1.0f/28, 1.0f/29, 1.0f/30, 1.0f/31
};

__global__ __launch_bounds__(256)
void diou3d_loss_kernel(const float* __restrict__ pred,
                        const float* __restrict__ tgt,
                        float* __restrict__ out, int n)
{
    int i = blockIdx.x * blockDim.x + threadIdx.x;
    float loss = 0.0f;
    if (i < n) {
        float p[7], t[7];
#pragma unroll
        for (int k = 0; k < 7; k++) { p[k] = pred[i * 7 + k]; t[k] = tgt[i * 7 + k]; }

        float cp, sp, ct, st;
        __sincosf(p[6], &sp, &cp);
        __sincosf(t[6], &st, &ct);

        // ---- box2's axis-aligned frame ----
        float W = 0.5f * t[3], H = 0.5f * t[4];
        float w1h = 0.5f * p[3], h1h = 0.5f * p[4];
        float cd = cp * ct + sp * st;                     // cos(a1-a2)
        float sd = sp * ct - cp * st;                     // sin(a1-a2)
        float dx0 = p[0] - t[0], dy0 = p[1] - t[1];
        float qx =  ct * dx0 + st * dy0;
        float qy = -st * dx0 + ct * dy0;

        // box1 corners in frame2 (reference order: (+,+)(-,+)(-,-)(+,-))
        float c1x[4], c1y[4];
        {
            const float sx[4] = {1.0f, -1.0f, -1.0f, 1.0f};
            const float sy[4] = {1.0f, 1.0f, -1.0f, -1.0f};
#pragma unroll
            for (int k = 0; k < 4; k++) {
                float ox = sx[k] * w1h, oy = sy[k] * h1h;
                c1x[k] = qx + ox * cd - oy * sd;
                c1y[k] = qy + ox * sd + oy * cd;
            }
        }

        float2 vv[24];
        int cnt = 0;
        float sumx = 0.0f, sumy = 0.0f;

        // corners of box1 inside box2
        {
            float bx = fmaf(TOL_F, t[3], W);
            float by = fmaf(TOL_F, t[4], H);
#pragma unroll
            for (int k = 0; k < 4; k++) {
                if (fabsf(c1x[k]) < bx && fabsf(c1y[k]) < by) {
                    vv[cnt] = make_float2(c1x[k], c1y[k]);
                    sumx += c1x[k]; sumy += c1y[k]; cnt++;
                }
            }
        }
        // corners of box2 inside box1
        {
            float bx = fmaf(TOL_F, p[3], w1h);
            float by = fmaf(TOL_F, p[4], h1h);
            const float kxs[4] = {1.0f, -1.0f, -1.0f, 1.0f};
            const float kys[4] = {1.0f, 1.0f, -1.0f, -1.0f};
#pragma unroll
            for (int k = 0; k < 4; k++) {
                float kx = kxs[k] * W, ky = kys[k] * H;
                float rx = kx - qx, ry = ky - qy;
                float mx = cd * rx + sd * ry;
                float my = -sd * rx + cd * ry;
                if (fabsf(mx) < bx && fabsf(my) < by) {
                    vv[cnt] = make_float2(kx, ky);
                    sumx += kx; sumy += ky; cnt++;
                }
            }
        }

        // box1 edges vs box2 edge lines (reference's sign-flipped u -> phantom windows):
        //   x=+W : yv in (-3H,-H)   x=-W : yv in (H,3H)
        //   y=+H : xv in (W,3W)     y=-H : xv in (-3W,-W)
        // Division-free t-gate: t in (0,1) iff (X-x1)*d > 0 && |X-x1| < |d|.
        float W3 = 3.0f * W, H3 = 3.0f * H;
#pragma unroll
        for (int a = 0; a < 4; a++) {
            float x1 = c1x[a], y1 = c1y[a];
            float dxe = c1x[(a + 1) & 3] - x1, dye = c1y[(a + 1) & 3] - y1;
            float adx = fabsf(dxe), ady = fabsf(dye);

            float nx = W - x1;                           // line x=+W
            if (nx * dxe > 0.0f && fabsf(nx) < adx) {
                float yv = fmaf(__fdividef(nx, dxe), dye, y1);
                if (yv > -H3 && yv < -H) {
                    vv[cnt] = make_float2(W, yv);
                    sumx += W; sumy += yv; cnt++;
                }
            }
            nx = -W - x1;                                // line x=-W
            if (nx * dxe > 0.0f && fabsf(nx) < adx) {
                float yv = fmaf(__fdividef(nx, dxe), dye, y1);
                if (yv > H && yv < H3) {
                    vv[cnt] = make_float2(-W, yv);
                    sumx += -W; sumy += yv; cnt++;
                }
            }
            float ny = H - y1;                           // line y=+H
            if (ny * dye > 0.0f && fabsf(ny) < ady) {
                float xv = fmaf(__fdividef(ny, dye), dxe, x1);
                if (xv > W && xv < W3) {
                    vv[cnt] = make_float2(xv, H);
                    sumx += xv; sumy += H; cnt++;
                }
            }
            ny = -H - y1;                                // line y=-H
            if (ny * dye > 0.0f && fabsf(ny) < ady) {
                float xv = fmaf(__fdividef(ny, dye), dxe, x1);
                if (xv > -W3 && xv < -W) {
                    vv[cnt] = make_float2(xv, -H);
                    sumx += xv; sumy += -H; cnt++;
                }
            }
        }

        // ---- pseudo-angle keys around mean + insertion sort + shoelace (R10-proven) ----
        float area = 0.0f;
        if (cnt > 0) {
            unsigned key[24];
            float inv = c_inv[cnt];
            float mx = sumx * inv, my = sumy * inv;
            for (int k = 0; k < cnt; k++) {
                float x = vv[k].x - mx, y = vv[k].y - my;
                float tt = __fdividef(x, fabsf(x) + fabsf(y) + 1e-30f);
                float a = (y >= 0.0f) ? (1.0f - tt) : (3.0f + tt);
                key[k] = (__float_as_uint(a) & 0xFFFFFFE0u) | (unsigned)k;
            }
            for (int k = 1; k < cnt; k++) {
                unsigned a = key[k];
                int j = k - 1;
                while (j >= 0 && key[j] > a) { key[j + 1] = key[j]; j--; }
                key[j + 1] = a;
            }
            unsigned k0 = key[0] & 31u;
            float fx = vv[k0].x - mx, fy = vv[k0].y - my;
            float px = fx, py = fy, s = 0.0f;
            for (int k = 1; k < cnt; k++) {
                unsigned id = key[k] & 31u;
                float x = vv[id].x - mx, y = vv[id].y - my;
                s += px * y - py * x;
                px = x; py = y;
            }
            s += px * fy - py * fx;
            area = 0.5f * fabsf(s);
        }

        // ---- 3D IoU ----
        float zov = fmaxf(fminf(p[2] + 0.5f * p[5], t[2] + 0.5f * t[5]) -
                          fmaxf(p[2] - 0.5f * p[5], t[2] - 0.5f * t[5]), 0.0f);
        float inter3 = area * zov;
        float vol1 = p[3] * p[4] * p[5];
        float vol2 = t[3] * t[4] * t[5];
        float iou = __fdividef(inter3, vol1 + vol2 - inter3);  // 0/0 -> NaN preserved
        if (isnan(iou)) iou = 0.0f;

        float ctd = dx0 * dx0 + dy0 * dy0 + (p[2] - t[2]) * (p[2] - t[2]);

        // closed-form corner distance (verified R5)
        float alpha = p[3] * cp - t[3] * ct;
        float gamma = p[3] * sp - t[3] * st;
        float beta  = p[5] * sp - t[5] * st;
        float delta = p[5] * cp - t[5] * ct;
        float epsi  = p[4] - t[4];
        float cnd = ctd + 0.25f * (alpha * alpha + beta * beta + gamma * gamma +
                                   delta * delta + epsi * epsi);

        float did = t[3] * t[3] + t[4] * t[4] + t[5] * t[5];
        float sreg = ctd + cnd;
        float reg = __fdividef(sreg, sreg + did + LOSS_EPS_F);
        loss = 1.0f - iou + reg;
    }

    // ---- block reduction ----
#pragma unroll
    for (int off = 16; off; off >>= 1)
        loss += __shfl_down_sync(0xffffffff, loss, off);

    __shared__ float warpsum[8];
    int lane = threadIdx.x & 31, wid = threadIdx.x >> 5;
    if (lane == 0) warpsum[wid] = loss;
    __syncthreads();

    __shared__ bool amLast;
    if (wid == 0) {
        float s = (lane < 8) ? warpsum[lane] : 0.0f;
#pragma unroll
        for (int off = 4; off; off >>= 1)
            s += __shfl_down_sync(0xffffffff, s, off);
        if (lane == 0) {
            g_partial[blockIdx.x] = s;
            __threadfence();
            unsigned prev = atomicAdd(&g_arrived, 1u);
            amLast = (prev == gridDim.x - 1);
        }
    }
    __syncthreads();

    // last block: reduce all partials, write result, reset counter
    if (amLast) {
        int nb = gridDim.x;
        float s = 0.0f;
        for (int k = threadIdx.x; k < nb; k += 256) s += g_partial[k];
#pragma unroll
        for (int off = 16; off; off >>= 1)
            s += __shfl_down_sync(0xffffffff, s, off);
        if (lane == 0) warpsum[wid] = s;
        __syncthreads();
        if (wid == 0) {
            float s2 = (lane < 8) ? warpsum[lane] : 0.0f;
#pragma unroll
            for (int off = 4; off; off >>= 1)
                s2 += __shfl_down_sync(0xffffffff, s2, off);
            if (lane == 0) {
                out[0] = s2 * (1.0f / (float)n);
                g_arrived = 0;   // reset for next graph replay
            }
        }
    }
}

extern "C" void kernel_launch(void* const* d_in, const int* in_sizes, int n_in,
                              void* d_out, int out_size)
{
    const float* pred = (const float*)d_in[0];
    const float* tgt  = (const float*)d_in[1];
    float* out = (float*)d_out;
    int n = in_sizes[0] / 7;
    int blocks = (n + 255) / 256;
    if (blocks > MAX_BLOCKS) blocks = MAX_BLOCKS;  // n fixed at 262144 -> 1024

    diou3d_loss_kernel<<<blocks, 256>>>(pred, tgt, out, n);
}